// round 15
// baseline (speedup 1.0000x reference)
#include <cuda_runtime.h>
#include <cuda_bf16.h>
#include <cstdint>

#define B_   128
#define T_   1024
#define D_   256
#define HS_  512
#define G4_  2048
#define M1_  (B_ * T_)

#define RCTA 128
#define RTHR 512

// ---------------- device scratch ----------------
__device__ float g_xw[(size_t)M1_ * G4_];            // [(row*T+t)*2048 + pc]
__device__ uint4 g_uf[64 * 32 * 4 * 32];             // U frags [cg][kt][nt][lane]
__device__ uint4 g_xfh[(size_t)8192 * 16 * 32];      // x A-frags hi
__device__ uint4 g_xfl[(size_t)8192 * 16 * 32];      // x A-frags lo
__device__ uint4 g_wf[16 * 16 * 16 * 32];            // W B-frags
__device__ uint4 g_hfh[2][8 * 32 * 32];              // h bf16 A-frags (single precision level)
__device__ unsigned int g_bar_l1[16 * 32];           // leaves: [mh*8 + leaf]*32
__device__ unsigned int g_bar_l2v[2 * 32];           // roots per half
__device__ unsigned int g_bar_epochv[2 * 32];        // epochs per half

// ---------------- helpers ----------------
__device__ __forceinline__ uint32_t packbf(__nv_bfloat16 a, __nv_bfloat16 b) {
    return ((uint32_t)(*(uint16_t*)&b) << 16) | (uint32_t)(*(uint16_t*)&a);
}
__device__ __forceinline__ void split2(float a, float b, uint32_t& hi, uint32_t& lo) {
    __nv_bfloat16 ah = __float2bfloat16(a), bh = __float2bfloat16(b);
    __nv_bfloat16 al = __float2bfloat16(a - __bfloat162float(ah));
    __nv_bfloat16 bl = __float2bfloat16(b - __bfloat162float(bh));
    hi = packbf(ah, bh);
    lo = packbf(al, bl);
}
__device__ __forceinline__ void mma16816(float* d, const uint4& a, uint32_t b0, uint32_t b1) {
    asm volatile(
        "mma.sync.aligned.m16n8k16.row.col.f32.bf16.bf16.f32 "
        "{%0,%1,%2,%3}, {%4,%5,%6,%7}, {%8,%9}, {%0,%1,%2,%3};"
        : "+f"(d[0]), "+f"(d[1]), "+f"(d[2]), "+f"(d[3])
        : "r"(a.x), "r"(a.y), "r"(a.z), "r"(a.w), "r"(b0), "r"(b1));
}
__device__ __forceinline__ unsigned atom_add_release(unsigned* p, unsigned v) {
    unsigned old;
    asm volatile("atom.release.gpu.global.add.u32 %0, [%1], %2;"
                 : "=r"(old) : "l"(p), "r"(v) : "memory");
    return old;
}
__device__ __forceinline__ void st_release(unsigned* p, unsigned v) {
    asm volatile("st.release.gpu.global.u32 [%0], %1;" :: "l"(p), "r"(v) : "memory");
}
__device__ __forceinline__ unsigned ld_acquire(const unsigned* p) {
    unsigned v;
    asm volatile("ld.acquire.gpu.global.u32 %0, [%1];" : "=r"(v) : "l"(p) : "memory");
    return v;
}
__device__ __forceinline__ float sigmoid_fast(float x) { return 1.f / (1.f + __expf(-x)); }
__device__ __forceinline__ float tanh_fast(float x) { float e = __expf(2.f * x); return 1.f - 2.f / (e + 1.f); }

// orig gate col c = gate*512 + hcol -> pc = (hcol/8)*32 + gate*8 + hcol%8
__device__ __forceinline__ int cperm(int c) {
    int g = c >> 9, hc = c & 511;
    return ((hc >> 3) << 5) + (g << 3) + (hc & 7);
}

// ---------------- merged prep: split_xf | wf | uf | init ----------------
__global__ __launch_bounds__(256) void prep_all(const float* __restrict__ x,
                                                const float* __restrict__ Wm,
                                                const float* __restrict__ U) {
    const int bid = blockIdx.x;
    const int tid = threadIdx.x;
    if (bid < 16384) {
        size_t i = (size_t)bid * 256 + tid;
        int l = (int)(i & 31), kt = (int)((i >> 5) & 15);
        int rg = (int)(i >> 9);
        int row = rg * 16 + (l >> 2);
        int k0 = kt * 16 + (l & 3) * 2;
        uint32_t hi[4], lo[4];
#pragma unroll
        for (int kh = 0; kh < 2; kh++)
#pragma unroll
            for (int rh = 0; rh < 2; rh++) {
                float2 v = *(const float2*)&x[(size_t)(row + 8 * rh) * D_ + k0 + 8 * kh];
                split2(v.x, v.y, hi[kh * 2 + rh], lo[kh * 2 + rh]);
            }
        g_xfh[i] = make_uint4(hi[0], hi[1], hi[2], hi[3]);
        g_xfl[i] = make_uint4(lo[0], lo[1], lo[2], lo[3]);
    } else if (bid < 16896) {
        int i = (bid - 16384) * 256 + tid;
        int l = i & 31, nc = (i >> 5) & 15, kt = (i >> 9) & 15, cb = i >> 13;
        int n = cb * 128 + nc * 8 + (l >> 2);
        int k0 = kt * 16 + (l & 3) * 2;
        float u00 = Wm[(size_t)k0 * G4_ + n];
        float u01 = Wm[(size_t)(k0 + 1) * G4_ + n];
        float u10 = Wm[(size_t)(k0 + 8) * G4_ + n];
        float u11 = Wm[(size_t)(k0 + 9) * G4_ + n];
        uint32_t b0h, b0l, b1h, b1l;
        split2(u00, u01, b0h, b0l);
        split2(u10, u11, b1h, b1l);
        g_wf[i] = make_uint4(b0h, b1h, b0l, b1l);
    } else if (bid < 17920) {
        int i = (bid - 16896) * 256 + tid;
        int l = i & 31, nt = (i >> 5) & 3, kt = (i >> 7) & 31, cg = i >> 12;
        int n = nt * 8 + (l >> 2);
        int k0 = kt * 16 + (l & 3) * 2;
        int c = (n >> 3) * 512 + cg * 8 + (n & 7);
        float u00 = U[(size_t)k0 * G4_ + c];
        float u01 = U[(size_t)(k0 + 1) * G4_ + c];
        float u10 = U[(size_t)(k0 + 8) * G4_ + c];
        float u11 = U[(size_t)(k0 + 9) * G4_ + c];
        uint32_t b0h, b0l, b1h, b1l;
        split2(u00, u01, b0h, b0l);
        split2(u10, u11, b1h, b1l);
        g_uf[i] = make_uint4(b0h, b1h, b0l, b1l);
    } else {
        int i = (bid - 17920) * 256 + tid;           // 0..8191
        if (i < 16 * 32) g_bar_l1[i] = 0u;
        if (i < 2 * 32) { g_bar_l2v[i] = 0u; g_bar_epochv[i] = 0u; }
        g_hfh[0][i] = make_uint4(0, 0, 0, 0);
    }
}

// ---------------- phase 1: xW = x @ W + bias (mma.sync, 3-product split) -------
__global__ __launch_bounds__(256) void xw_mma(const float* __restrict__ bias) {
    const int tid = threadIdx.x;
    const int w = tid >> 5, l = tid & 31;
    const int cb = blockIdx.x, rb = blockIdx.y;
    const int wr = w & 3, wc = w >> 2;

    float acc[2][8][4];
#pragma unroll
    for (int mt = 0; mt < 2; mt++)
#pragma unroll
        for (int nt = 0; nt < 8; nt++)
#pragma unroll
            for (int q = 0; q < 4; q++) acc[mt][nt][q] = 0.f;

#pragma unroll 4
    for (int kt = 0; kt < 16; kt++) {
        uint4 bf[8];
#pragma unroll
        for (int nt = 0; nt < 8; nt++)
            bf[nt] = __ldg(&g_wf[(((cb * 16 + kt) * 16) + wc * 8 + nt) * 32 + l]);
#pragma unroll
        for (int mt = 0; mt < 2; mt++) {
            size_t rg = (size_t)rb * 8 + wr * 2 + mt;
            uint4 ah = __ldg(&g_xfh[(rg * 16 + kt) * 32 + l]);
            uint4 al = __ldg(&g_xfl[(rg * 16 + kt) * 32 + l]);
#pragma unroll
            for (int nt = 0; nt < 8; nt++) {
                mma16816(acc[mt][nt], ah, bf[nt].x, bf[nt].y);
                mma16816(acc[mt][nt], ah, bf[nt].z, bf[nt].w);
                mma16816(acc[mt][nt], al, bf[nt].x, bf[nt].y);
            }
        }
    }

#pragma unroll
    for (int mt = 0; mt < 2; mt++) {
        int r0 = rb * 128 + wr * 32 + mt * 16 + (l >> 2);
#pragma unroll
        for (int nt = 0; nt < 8; nt++) {
            int c = cb * 128 + wc * 64 + nt * 8 + (l & 3) * 2;
            int pc = cperm(c);
            float2 bv = __ldg((const float2*)&bias[c]);
            *(float2*)&g_xw[(size_t)r0 * G4_ + pc] =
                make_float2(acc[mt][nt][0] + bv.x, acc[mt][nt][1] + bv.y);
            *(float2*)&g_xw[(size_t)(r0 + 8) * G4_ + pc] =
                make_float2(acc[mt][nt][2] + bv.x, acc[mt][nt][3] + bv.y);
        }
    }
}

// ---------------- phase 2: persistent mma.sync recurrence ----------------
// 128 CTAs x 512 thr. cta = cg*2 + mh. Two INDEPENDENT sub-recurrences (mh halves),
// each with its own 64-wide tree barrier. Warp (mq,kq): M=16, N=32, K=128.
// h single-bf16; U split (2 products/mma-slot).
#define SPAD  34
#define XPAD  36
#define SRED_ELEMS (4 * 64 * SPAD)
#define SMEM_ELEMS (SRED_ELEMS + 64 * XPAD)

__global__ __launch_bounds__(RTHR, 1) void lstm_rec(float* __restrict__ out,
                                                    int write_hc) {
    extern __shared__ float smemf[];
    float* sred = smemf;
    float* xw_s = smemf + SRED_ELEMS;

    const int tid = threadIdx.x;
    const int w = tid >> 5, l = tid & 31;
    const int cta = blockIdx.x;
    const int cg = cta >> 1, mh = cta & 1;
    const int mq = w >> 2, kq = w & 3;

    // epilogue role (tid < 256): 2 cells = row x hcols {2hp, 2hp+1}
    const int rl = (tid & 255) >> 2, hp = tid & 3;
    const int row_g = mh * 64 + rl;
    const size_t fragidx = ((size_t)(row_g >> 4) * 32 + (cg >> 1)) * 32 + (row_g & 7) * 4 + hp;
    const int regb = (cg & 1) * 2 + ((row_g >> 3) & 1);

    const uint4* __restrict__ ub = g_uf + (size_t)cg * 4096;

    const int xw_rwl = tid >> 3;                     // local row 0..63
    const int xw_co  = cg * 32 + (tid & 7) * 4;
    const int aslot_base = ((mh * 4 + mq) * 32) * 32 + l;

    // per-half barrier pointers
    unsigned* leaf  = &g_bar_l1[(mh * 8 + (cg & 7)) * 32];
    unsigned* root  = &g_bar_l2v[mh * 32];
    unsigned* epoch = &g_bar_epochv[mh * 32];

    float creg[2] = {0.f, 0.f};
    float hlast[2];

    // xw prefetch for t = 0
    float4 xr = __ldcg((const float4*)&g_xw[((size_t)(mh * 64 + xw_rwl) * T_ + 0) * G4_ + xw_co]);

    for (int t = 0; t < T_; t++) {
        const int p = t & 1;
        const uint4* __restrict__ Ah = g_hfh[p];

        float acc[4][4];
#pragma unroll
        for (int nt = 0; nt < 4; nt++)
#pragma unroll
            for (int q = 0; q < 4; q++) acc[nt][q] = 0.f;

        // ---- mainloop: kt = kq*8 + i, double-buffered A (single bf16) ----
        uint4 ahb[2];
        ahb[0] = __ldcg(&Ah[aslot_base + (kq * 8) * 32]);
#pragma unroll
        for (int i = 0; i < 8; i++) {
            const int cur = i & 1;
            if (i < 7)
                ahb[cur ^ 1] = __ldcg(&Ah[aslot_base + (kq * 8 + i + 1) * 32]);
            const int kt = kq * 8 + i;
            uint4 bf[4];
#pragma unroll
            for (int nt = 0; nt < 4; nt++)
                bf[nt] = __ldg(&ub[(kt * 4 + nt) * 32 + l]);
#pragma unroll
            for (int nt = 0; nt < 4; nt++) {
                mma16816(acc[nt], ahb[cur], bf[nt].x, bf[nt].y);   // h * U_hi
                mma16816(acc[nt], ahb[cur], bf[nt].z, bf[nt].w);   // h * U_lo
            }
        }

        // ---- partials + xw to smem ----
        {
            const int row0 = (l >> 2), n0 = 2 * (l & 3);
#pragma unroll
            for (int nt = 0; nt < 4; nt++) {
                int s = (kq * 64 + mq * 16 + row0) * SPAD + nt * 8 + n0;
                *(float2*)&sred[s]            = make_float2(acc[nt][0], acc[nt][1]);
                *(float2*)&sred[s + 8 * SPAD] = make_float2(acc[nt][2], acc[nt][3]);
            }
            *(float4*)&xw_s[xw_rwl * XPAD + (tid & 7) * 4] = xr;
        }
        __syncthreads();

        // ---- reduce + cell update (tid < 256) ----
        float hnew[2];
        if (tid < 256) {
            float2 gsum[4];
#pragma unroll
            for (int g = 0; g < 4; g++) {
                float2 s = *(const float2*)&xw_s[rl * XPAD + g * 8 + 2 * hp];
#pragma unroll
                for (int q2 = 0; q2 < 4; q2++) {
                    float2 v = *(const float2*)&sred[(q2 * 64 + rl) * SPAD + g * 8 + 2 * hp];
                    s.x += v.x; s.y += v.y;
                }
                gsum[g] = s;
            }
#pragma unroll
            for (int q = 0; q < 2; q++) {
                float gi = q ? gsum[0].y : gsum[0].x;
                float gf = q ? gsum[1].y : gsum[1].x;
                float gg = q ? gsum[2].y : gsum[2].x;
                float go = q ? gsum[3].y : gsum[3].x;
                float iv = sigmoid_fast(gi);
                float fv = sigmoid_fast(gf);
                float gv = tanh_fast(gg);
                float ov = sigmoid_fast(go);
                float c = fv * creg[q] + iv * gv;
                creg[q] = c;
                float h = ov * tanh_fast(c);
                hnew[q] = h;
                hlast[q] = h;
            }
            // h fragment write (single bf16) before barrier arrival
            uint32_t hi = packbf(__float2bfloat16(hnew[0]), __float2bfloat16(hnew[1]));
            *(uint32_t*)((char*)g_hfh[1 - p] + fragidx * 16 + regb * 4) = hi;
        }

        if (t < T_ - 1) {
            const unsigned tgt = (unsigned)(t + 1);
            __syncthreads();   // all h stores precede tid0's release-arrive
            if (tid == 0) {
                unsigned old = atom_add_release(leaf, 1u);
                if (old == 8u * tgt - 1u) {
                    unsigned old2 = atom_add_release(root, 1u);
                    if (old2 == 8u * tgt - 1u)
                        st_release(epoch, tgt);
                }
            }
            // overlap with the barrier: out store + next-step xw prefetch
            if (tid < 256)
                *(float2*)&out[((size_t)row_g * T_ + t) * HS_ + cg * 8 + 2 * hp] =
                    make_float2(hnew[0], hnew[1]);
            xr = __ldcg((const float4*)&g_xw[((size_t)(mh * 64 + xw_rwl) * T_ + (t + 1)) * G4_ + xw_co]);
            if (tid == 0) {
                while (ld_acquire(epoch) < tgt) { }
            }
            __syncthreads();
        } else {
            if (tid < 256)
                *(float2*)&out[((size_t)row_g * T_ + t) * HS_ + cg * 8 + 2 * hp] =
                    make_float2(hnew[0], hnew[1]);
        }
    }

    if (write_hc && tid < 256) {
        const size_t OH = (size_t)B_ * T_ * HS_;
        *(float2*)&out[OH + (size_t)row_g * HS_ + cg * 8 + 2 * hp] =
            make_float2(hlast[0], hlast[1]);
        *(float2*)&out[OH + (size_t)B_ * HS_ + (size_t)row_g * HS_ + cg * 8 + 2 * hp] =
            make_float2(creg[0], creg[1]);
    }
}

// ---------------- launch ----------------
extern "C" void kernel_launch(void* const* d_in, const int* in_sizes, int n_in,
                              void* d_out, int out_size) {
    const float* x    = (const float*)d_in[0];
    const float* Wm   = (const float*)d_in[1];
    const float* U    = (const float*)d_in[2];
    const float* bias = (const float*)d_in[3];
    float* out = (float*)d_out;
    (void)in_sizes; (void)n_in;

    const int smem_rec = SMEM_ELEMS * (int)sizeof(float);   // 44032 B
    cudaFuncSetAttribute(lstm_rec, cudaFuncAttributeMaxDynamicSharedMemorySize, smem_rec);

    const long long need_hc = (long long)B_ * T_ * HS_ + 2LL * B_ * HS_;
    int write_hc = ((long long)out_size >= need_hc) ? 1 : 0;

    prep_all<<<17952, 256>>>(x, Wm, U);
    xw_mma<<<dim3(16, 1024), 256>>>(bias);
    lstm_rec<<<RCTA, RTHR, smem_rec>>>(out, write_hc);
}

// round 17
// speedup vs baseline: 1.4133x; 1.4133x over previous
#include <cuda_runtime.h>
#include <cuda_bf16.h>
#include <cstdint>

#define B_   128
#define T_   1024
#define D_   256
#define HS_  512
#define G4_  2048
#define M1_  (B_ * T_)

#define RCTA 128
#define RTHR 512

// ---------------- device scratch ----------------
__device__ float g_xw[(size_t)M1_ * G4_];            // [(row*T+t)*2048 + pc]
__device__ uint2 g_uf2[64 * 32 * 4 * 32];            // U frags bf16 [cg][kt][nt][lane] = {b0,b1}
__device__ uint4 g_xfh[(size_t)8192 * 16 * 32];      // x A-frags hi
__device__ uint4 g_xfl[(size_t)8192 * 16 * 32];      // x A-frags lo
__device__ uint4 g_wf[16 * 16 * 16 * 32];            // W B-frags (split, for accurate xW)
__device__ uint4 g_hfh[2][8 * 32 * 32];              // h hi A-frags
__device__ uint4 g_hfl[2][8 * 32 * 32];              // h lo A-frags
__device__ unsigned int g_bar_l1[16 * 32];           // tree barrier leaves (128B stride)
__device__ unsigned int g_bar_l2;                    // tree barrier root
__device__ unsigned int g_bar_epoch;

// ---------------- helpers ----------------
__device__ __forceinline__ uint32_t packbf(__nv_bfloat16 a, __nv_bfloat16 b) {
    return ((uint32_t)(*(uint16_t*)&b) << 16) | (uint32_t)(*(uint16_t*)&a);
}
__device__ __forceinline__ void split2(float a, float b, uint32_t& hi, uint32_t& lo) {
    __nv_bfloat16 ah = __float2bfloat16(a), bh = __float2bfloat16(b);
    __nv_bfloat16 al = __float2bfloat16(a - __bfloat162float(ah));
    __nv_bfloat16 bl = __float2bfloat16(b - __bfloat162float(bh));
    hi = packbf(ah, bh);
    lo = packbf(al, bl);
}
__device__ __forceinline__ void mma16816(float* d, const uint4& a, uint32_t b0, uint32_t b1) {
    asm volatile(
        "mma.sync.aligned.m16n8k16.row.col.f32.bf16.bf16.f32 "
        "{%0,%1,%2,%3}, {%4,%5,%6,%7}, {%8,%9}, {%0,%1,%2,%3};"
        : "+f"(d[0]), "+f"(d[1]), "+f"(d[2]), "+f"(d[3])
        : "r"(a.x), "r"(a.y), "r"(a.z), "r"(a.w), "r"(b0), "r"(b1));
}
__device__ __forceinline__ unsigned atom_add_release(unsigned* p, unsigned v) {
    unsigned old;
    asm volatile("atom.release.gpu.global.add.u32 %0, [%1], %2;"
                 : "=r"(old) : "l"(p), "r"(v) : "memory");
    return old;
}
__device__ __forceinline__ void st_release(unsigned* p, unsigned v) {
    asm volatile("st.release.gpu.global.u32 [%0], %1;" :: "l"(p), "r"(v) : "memory");
}
__device__ __forceinline__ unsigned ld_acquire(const unsigned* p) {
    unsigned v;
    asm volatile("ld.acquire.gpu.global.u32 %0, [%1];" : "=r"(v) : "l"(p) : "memory");
    return v;
}
__device__ __forceinline__ float sigmoid_fast(float x) { return 1.f / (1.f + __expf(-x)); }
__device__ __forceinline__ float tanh_fast(float x) { float e = __expf(2.f * x); return 1.f - 2.f / (e + 1.f); }

// orig gate col c = gate*512 + hcol -> pc = (hcol/8)*32 + gate*8 + hcol%8
__device__ __forceinline__ int cperm(int c) {
    int g = c >> 9, hc = c & 511;
    return ((hc >> 3) << 5) + (g << 3) + (hc & 7);
}

// ---------------- merged prep: split_xf | wf | uf | init ----------------
__global__ __launch_bounds__(256) void prep_all(const float* __restrict__ x,
                                                const float* __restrict__ Wm,
                                                const float* __restrict__ U) {
    const int bid = blockIdx.x;
    const int tid = threadIdx.x;
    if (bid < 16384) {
        size_t i = (size_t)bid * 256 + tid;
        int l = (int)(i & 31), kt = (int)((i >> 5) & 15);
        int rg = (int)(i >> 9);
        int row = rg * 16 + (l >> 2);
        int k0 = kt * 16 + (l & 3) * 2;
        uint32_t hi[4], lo[4];
#pragma unroll
        for (int kh = 0; kh < 2; kh++)
#pragma unroll
            for (int rh = 0; rh < 2; rh++) {
                float2 v = *(const float2*)&x[(size_t)(row + 8 * rh) * D_ + k0 + 8 * kh];
                split2(v.x, v.y, hi[kh * 2 + rh], lo[kh * 2 + rh]);
            }
        g_xfh[i] = make_uint4(hi[0], hi[1], hi[2], hi[3]);
        g_xfl[i] = make_uint4(lo[0], lo[1], lo[2], lo[3]);
    } else if (bid < 16896) {
        int i = (bid - 16384) * 256 + tid;
        int l = i & 31, nc = (i >> 5) & 15, kt = (i >> 9) & 15, cb = i >> 13;
        int n = cb * 128 + nc * 8 + (l >> 2);
        int k0 = kt * 16 + (l & 3) * 2;
        float u00 = Wm[(size_t)k0 * G4_ + n];
        float u01 = Wm[(size_t)(k0 + 1) * G4_ + n];
        float u10 = Wm[(size_t)(k0 + 8) * G4_ + n];
        float u11 = Wm[(size_t)(k0 + 9) * G4_ + n];
        uint32_t b0h, b0l, b1h, b1l;
        split2(u00, u01, b0h, b0l);
        split2(u10, u11, b1h, b1l);
        g_wf[i] = make_uint4(b0h, b1h, b0l, b1l);
    } else if (bid < 17920) {
        int i = (bid - 16896) * 256 + tid;
        int l = i & 31, nt = (i >> 5) & 3, kt = (i >> 7) & 31, cg = i >> 12;
        int n = nt * 8 + (l >> 2);
        int k0 = kt * 16 + (l & 3) * 2;
        int c = (n >> 3) * 512 + cg * 8 + (n & 7);
        float u00 = U[(size_t)k0 * G4_ + c];
        float u01 = U[(size_t)(k0 + 1) * G4_ + c];
        float u10 = U[(size_t)(k0 + 8) * G4_ + c];
        float u11 = U[(size_t)(k0 + 9) * G4_ + c];
        // single-bf16 U fragments (round-to-nearest)
        uint32_t b0 = packbf(__float2bfloat16(u00), __float2bfloat16(u01));
        uint32_t b1 = packbf(__float2bfloat16(u10), __float2bfloat16(u11));
        g_uf2[i] = make_uint2(b0, b1);
    } else {
        int i = (bid - 17920) * 256 + tid;           // 0..8191
        if (i == 0) { g_bar_l2 = 0; g_bar_epoch = 0; }
        if (i < 16 * 32) g_bar_l1[i] = 0u;
        g_hfh[0][i] = make_uint4(0, 0, 0, 0);
        g_hfl[0][i] = make_uint4(0, 0, 0, 0);
    }
}

// ---------------- phase 1: xW = x @ W + bias (mma.sync, 3-product split) -------
__global__ __launch_bounds__(256) void xw_mma(const float* __restrict__ bias) {
    const int tid = threadIdx.x;
    const int w = tid >> 5, l = tid & 31;
    const int cb = blockIdx.x, rb = blockIdx.y;
    const int wr = w & 3, wc = w >> 2;

    float acc[2][8][4];
#pragma unroll
    for (int mt = 0; mt < 2; mt++)
#pragma unroll
        for (int nt = 0; nt < 8; nt++)
#pragma unroll
            for (int q = 0; q < 4; q++) acc[mt][nt][q] = 0.f;

#pragma unroll 4
    for (int kt = 0; kt < 16; kt++) {
        uint4 bf[8];
#pragma unroll
        for (int nt = 0; nt < 8; nt++)
            bf[nt] = __ldg(&g_wf[(((cb * 16 + kt) * 16) + wc * 8 + nt) * 32 + l]);
#pragma unroll
        for (int mt = 0; mt < 2; mt++) {
            size_t rg = (size_t)rb * 8 + wr * 2 + mt;
            uint4 ah = __ldg(&g_xfh[(rg * 16 + kt) * 32 + l]);
            uint4 al = __ldg(&g_xfl[(rg * 16 + kt) * 32 + l]);
#pragma unroll
            for (int nt = 0; nt < 8; nt++) {
                mma16816(acc[mt][nt], ah, bf[nt].x, bf[nt].y);
                mma16816(acc[mt][nt], ah, bf[nt].z, bf[nt].w);
                mma16816(acc[mt][nt], al, bf[nt].x, bf[nt].y);
            }
        }
    }

#pragma unroll
    for (int mt = 0; mt < 2; mt++) {
        int r0 = rb * 128 + wr * 32 + mt * 16 + (l >> 2);
#pragma unroll
        for (int nt = 0; nt < 8; nt++) {
            int c = cb * 128 + wc * 64 + nt * 8 + (l & 3) * 2;
            int pc = cperm(c);
            float2 bv = __ldg((const float2*)&bias[c]);
            *(float2*)&g_xw[(size_t)r0 * G4_ + pc] =
                make_float2(acc[mt][nt][0] + bv.x, acc[mt][nt][1] + bv.y);
            *(float2*)&g_xw[(size_t)(r0 + 8) * G4_ + pc] =
                make_float2(acc[mt][nt][2] + bv.x, acc[mt][nt][3] + bv.y);
        }
    }
}

// ---------------- phase 2: persistent mma.sync recurrence ----------------
// 128 CTAs x 512 thr. cta = cg*2 + mh. Warp (mq=w>>2, kq=w&3): M=16, N=32, K=128.
// h split (Ah+Al, MLP 2); U single-bf16 (uint2 frags). 2 products per mma-slot:
// hi(h)*U + lo(h)*U. Single 16-leaf tree barrier (R14-proven).
#define SPAD  34
#define XPAD  36
#define SRED_ELEMS (4 * 64 * SPAD)
#define SMEM_ELEMS (SRED_ELEMS + 64 * XPAD)

__global__ __launch_bounds__(RTHR, 1) void lstm_rec(float* __restrict__ out,
                                                    int write_hc) {
    extern __shared__ float smemf[];
    float* sred = smemf;
    float* xw_s = smemf + SRED_ELEMS;

    const int tid = threadIdx.x;
    const int w = tid >> 5, l = tid & 31;
    const int cta = blockIdx.x;
    const int cg = cta >> 1, mh = cta & 1;
    const int mq = w >> 2, kq = w & 3;

    // epilogue role (tid < 256): 2 cells = row x hcols {2hp, 2hp+1}
    const int rl = (tid & 255) >> 2, hp = tid & 3;
    const int row_g = mh * 64 + rl;
    const size_t fragidx = ((size_t)(row_g >> 4) * 32 + (cg >> 1)) * 32 + (row_g & 7) * 4 + hp;
    const int regb = (cg & 1) * 2 + ((row_g >> 3) & 1);

    const uint2* __restrict__ ub = g_uf2 + (size_t)cg * 4096;

    const int xw_rwl = tid >> 3;                     // local row 0..63
    const int xw_co  = cg * 32 + (tid & 7) * 4;
    const int aslot_base = ((mh * 4 + mq) * 32) * 32 + l;

    float creg[2] = {0.f, 0.f};
    float hlast[2];

    // xw prefetch for t = 0
    float4 xr = __ldcg((const float4*)&g_xw[((size_t)(mh * 64 + xw_rwl) * T_ + 0) * G4_ + xw_co]);

    for (int t = 0; t < T_; t++) {
        const int p = t & 1;
        const uint4* __restrict__ Ah = g_hfh[p];
        const uint4* __restrict__ Al = g_hfl[p];

        float acc[4][4];
#pragma unroll
        for (int nt = 0; nt < 4; nt++)
#pragma unroll
            for (int q = 0; q < 4; q++) acc[nt][q] = 0.f;

        // ---- mainloop: kt = kq*8 + i, double-buffered A (hi+lo, MLP 2) ----
        uint4 ahb[2], alb[2];
        {
            const int slot = aslot_base + (kq * 8) * 32;
            ahb[0] = __ldcg(&Ah[slot]);
            alb[0] = __ldcg(&Al[slot]);
        }
#pragma unroll
        for (int i = 0; i < 8; i++) {
            const int cur = i & 1;
            if (i < 7) {
                const int slot = aslot_base + (kq * 8 + i + 1) * 32;
                ahb[cur ^ 1] = __ldcg(&Ah[slot]);
                alb[cur ^ 1] = __ldcg(&Al[slot]);
            }
            const int kt = kq * 8 + i;
            uint2 bf[4];
#pragma unroll
            for (int nt = 0; nt < 4; nt++)
                bf[nt] = __ldg(&ub[(kt * 4 + nt) * 32 + l]);
#pragma unroll
            for (int nt = 0; nt < 4; nt++) {
                mma16816(acc[nt], ahb[cur], bf[nt].x, bf[nt].y);   // hi(h) * U
                mma16816(acc[nt], alb[cur], bf[nt].x, bf[nt].y);   // lo(h) * U
            }
        }

        // ---- partials + xw to smem ----
        {
            const int row0 = (l >> 2), n0 = 2 * (l & 3);
#pragma unroll
            for (int nt = 0; nt < 4; nt++) {
                int s = (kq * 64 + mq * 16 + row0) * SPAD + nt * 8 + n0;
                *(float2*)&sred[s]            = make_float2(acc[nt][0], acc[nt][1]);
                *(float2*)&sred[s + 8 * SPAD] = make_float2(acc[nt][2], acc[nt][3]);
            }
            *(float4*)&xw_s[xw_rwl * XPAD + (tid & 7) * 4] = xr;
        }
        __syncthreads();

        // ---- reduce + cell update (tid < 256) ----
        float hnew[2];
        if (tid < 256) {
            float2 gsum[4];
#pragma unroll
            for (int g = 0; g < 4; g++) {
                float2 s = *(const float2*)&xw_s[rl * XPAD + g * 8 + 2 * hp];
#pragma unroll
                for (int q2 = 0; q2 < 4; q2++) {
                    float2 v = *(const float2*)&sred[(q2 * 64 + rl) * SPAD + g * 8 + 2 * hp];
                    s.x += v.x; s.y += v.y;
                }
                gsum[g] = s;
            }
#pragma unroll
            for (int q = 0; q < 2; q++) {
                float gi = q ? gsum[0].y : gsum[0].x;
                float gf = q ? gsum[1].y : gsum[1].x;
                float gg = q ? gsum[2].y : gsum[2].x;
                float go = q ? gsum[3].y : gsum[3].x;
                float iv = sigmoid_fast(gi);
                float fv = sigmoid_fast(gf);
                float gv = tanh_fast(gg);
                float ov = sigmoid_fast(go);
                float c = fv * creg[q] + iv * gv;
                creg[q] = c;
                float h = ov * tanh_fast(c);
                hnew[q] = h;
                hlast[q] = h;
            }
            // h fragment write (hi + lo) before barrier arrival
            uint32_t hi, lo;
            split2(hnew[0], hnew[1], hi, lo);
            *(uint32_t*)((char*)g_hfh[1 - p] + fragidx * 16 + regb * 4) = hi;
            *(uint32_t*)((char*)g_hfl[1 - p] + fragidx * 16 + regb * 4) = lo;
        }

        if (t < T_ - 1) {
            const unsigned tgt = (unsigned)(t + 1);
            __syncthreads();   // all h stores precede tid0's release-arrive
            if (tid == 0) {
                unsigned old = atom_add_release(&g_bar_l1[(cta & 15) * 32], 1u);
                if (old == 8u * tgt - 1u) {
                    unsigned old2 = atom_add_release(&g_bar_l2, 1u);
                    if (old2 == 16u * tgt - 1u)
                        st_release(&g_bar_epoch, tgt);
                }
            }
            // overlap with the barrier: out store + next-step xw prefetch
            if (tid < 256)
                *(float2*)&out[((size_t)row_g * T_ + t) * HS_ + cg * 8 + 2 * hp] =
                    make_float2(hnew[0], hnew[1]);
            xr = __ldcg((const float4*)&g_xw[((size_t)(mh * 64 + xw_rwl) * T_ + (t + 1)) * G4_ + xw_co]);
            if (tid == 0) {
                while (ld_acquire(&g_bar_epoch) < tgt) { }
            }
            __syncthreads();
        } else {
            if (tid < 256)
                *(float2*)&out[((size_t)row_g * T_ + t) * HS_ + cg * 8 + 2 * hp] =
                    make_float2(hnew[0], hnew[1]);
        }
    }

    if (write_hc && tid < 256) {
        const size_t OH = (size_t)B_ * T_ * HS_;
        *(float2*)&out[OH + (size_t)row_g * HS_ + cg * 8 + 2 * hp] =
            make_float2(hlast[0], hlast[1]);
        *(float2*)&out[OH + (size_t)B_ * HS_ + (size_t)row_g * HS_ + cg * 8 + 2 * hp] =
            make_float2(creg[0], creg[1]);
    }
}

// ---------------- launch ----------------
extern "C" void kernel_launch(void* const* d_in, const int* in_sizes, int n_in,
                              void* d_out, int out_size) {
    const float* x    = (const float*)d_in[0];
    const float* Wm   = (const float*)d_in[1];
    const float* U    = (const float*)d_in[2];
    const float* bias = (const float*)d_in[3];
    float* out = (float*)d_out;
    (void)in_sizes; (void)n_in;

    const int smem_rec = SMEM_ELEMS * (int)sizeof(float);   // 44032 B
    cudaFuncSetAttribute(lstm_rec, cudaFuncAttributeMaxDynamicSharedMemorySize, smem_rec);

    const long long need_hc = (long long)B_ * T_ * HS_ + 2LL * B_ * HS_;
    int write_hc = ((long long)out_size >= need_hc) ? 1 : 0;

    prep_all<<<17952, 256>>>(x, Wm, U);
    xw_mma<<<dim3(16, 1024), 256>>>(bias);
    lstm_rec<<<RCTA, RTHR, smem_rec>>>(out, write_hc);
}